// round 4
// baseline (speedup 1.0000x reference)
#include <cuda_runtime.h>
#include <cuda_bf16.h>
#include <cstdint>

// MaxUnpooling2D scatter-add.
//   updates: f32 [8,128,128,256] = 33,554,432 elems (134 MB)
//   mask:    i32 same shape, values in [0, 2^24)
//   out:     f32 [8,256,256,256] = 134,217,728 elems (536 MB)
//   flat index = mask[i] + (elem_index >> 22) << 22   (batch offset = INPUT size)
//
// R4: 16 elems (4 float4) per thread, loads front-batched for MLP=8,
// 8192 blocks instead of 32768 to cut block churn.

static constexpr int N_UPD = 33554432;     // update elems (8 * 2^22)
static constexpr int N_OUT = 134217728;    // output elems (8 * 2^24)
static constexpr int BATCH_SHIFT = 22;     // flat_input_size = 2^22

__global__ void __launch_bounds__(256) zero_out_kernel(float4* __restrict__ out) {
    int i = blockIdx.x * 256 + threadIdx.x;
    out[i] = make_float4(0.f, 0.f, 0.f, 0.f);
}

// Each block covers 1024 consecutive float4 (4096 elems). 4096 | 2^22, so the
// whole block shares one batch base, computed once.
__global__ void __launch_bounds__(256) scatter_add_kernel(
    const float4* __restrict__ upd4,
    const int4*  __restrict__ mask4,
    float* __restrict__ out)
{
    int t = threadIdx.x;
    int block_base4 = blockIdx.x * 1024;                       // float4 units
    int base = ((block_base4 << 2) >> BATCH_SHIFT) << BATCH_SHIFT;  // batch * 2^22

    int4   m[4];
    float4 u[4];
    // Front-batch all 8 wide loads -> 8 outstanding LDG.128 per thread.
#pragma unroll
    for (int k = 0; k < 4; k++) m[k] = mask4[block_base4 + t + k * 256];
#pragma unroll
    for (int k = 0; k < 4; k++) u[k] = upd4[block_base4 + t + k * 256];

#pragma unroll
    for (int k = 0; k < 4; k++) {
        atomicAdd(out + (base + m[k].x), u[k].x);
        atomicAdd(out + (base + m[k].y), u[k].y);
        atomicAdd(out + (base + m[k].z), u[k].z);
        atomicAdd(out + (base + m[k].w), u[k].w);
    }
}

extern "C" void kernel_launch(void* const* d_in, const int* in_sizes, int n_in,
                              void* d_out, int out_size) {
    const float* updates = (const float*)d_in[0];
    const int*   mask    = (const int*)d_in[1];
    float* out = (float*)d_out;

    // Zero the full output (poisoned before timing; stale between graph replays).
    zero_out_kernel<<<(N_OUT / 4) / 256, 256>>>((float4*)out);

    // Scatter-add: 16 elems/thread, 8192 blocks.
    scatter_add_kernel<<<N_UPD / 4096, 256>>>(
        (const float4*)updates, (const int4*)mask, out);
}

// round 5
// speedup vs baseline: 1.1997x; 1.1997x over previous
#include <cuda_runtime.h>
#include <cuda_bf16.h>
#include <cstdint>

// MaxUnpooling2D scatter-add, L2-residency partitioned.
//   updates: f32 [8,128,128,256] = 33,554,432 elems (134 MB)
//   mask:    i32 same shape, values in [0, 2^24)
//   out:     f32 [8,256,256,256] = 134,217,728 elems (536 MB)
//   flat index = mask[i] + (elem_index >> 22) << 22
// Touched output range: [0, 2^24 + 7*2^22) = [0, 46,137,344) words (184.5 MB).
// Split into 2 partitions of 92.3 MB so each fits L2 (126 MB); zero a
// partition immediately before its scatter pass so atomics hit dirty-resident
// L2 lines. Streams use evict-first hints to preserve residency.

static constexpr int N_UPD    = 33554432;   // update elems (8 * 2^22)
static constexpr int N_OUT    = 134217728;  // output elems (8 * 2^24)
static constexpr int TOUCHED  = 46137344;   // 2^24 + 7*2^22
static constexpr int PART     = TOUCHED / 2;        // 23,068,672 words
static constexpr int BATCH_SHIFT = 22;

// Zero [lo4, lo4+n4) float4 with streaming stores (evict-first; these lines
// are not re-read before writeback).
__global__ void __launch_bounds__(256) zero_stream_kernel(float4* __restrict__ out) {
    int i = blockIdx.x * 256 + threadIdx.x;
    __stcs(out + i, make_float4(0.f, 0.f, 0.f, 0.f));
}

// Zero with default policy: lines stay dirty-resident in L2 for the
// immediately following scatter pass.
__global__ void __launch_bounds__(256) zero_resident_kernel(float4* __restrict__ out) {
    int i = blockIdx.x * 256 + threadIdx.x;
    out[i] = make_float4(0.f, 0.f, 0.f, 0.f);
}

// One scatter pass: stream mask+updates (evict-first), apply only atomics
// whose target lies in [lo, hi).
__global__ void __launch_bounds__(256) scatter_pass_kernel(
    const float4* __restrict__ upd4,
    const int4*  __restrict__ mask4,
    float* __restrict__ out,
    int lo, int hi)
{
    int i = blockIdx.x * 256 + threadIdx.x;        // float4 index
    int4   m = __ldcs(mask4 + i);
    float4 u = __ldcs(upd4 + i);
    int base = ((i << 2) >> BATCH_SHIFT) << BATCH_SHIFT;   // batch * 2^22

    int ix = base + m.x, iy = base + m.y, iz = base + m.z, iw = base + m.w;
    if (ix >= lo && ix < hi) atomicAdd(out + ix, u.x);
    if (iy >= lo && iy < hi) atomicAdd(out + iy, u.y);
    if (iz >= lo && iz < hi) atomicAdd(out + iz, u.z);
    if (iw >= lo && iw < hi) atomicAdd(out + iw, u.w);
}

extern "C" void kernel_launch(void* const* d_in, const int* in_sizes, int n_in,
                              void* d_out, int out_size) {
    const float* updates = (const float*)d_in[0];
    const int*   mask    = (const int*)d_in[1];
    float* out = (float*)d_out;

    const int n4_scatter = (N_UPD / 4) / 256;      // 32768 blocks per pass
    const int n4_part    = (PART / 4) / 256;       // 22528 blocks
    const int n4_tail    = ((N_OUT - TOUCHED) / 4) / 256;  // 86016 blocks

    // 1. Zero the never-touched tail [TOUCHED, N_OUT), streaming.
    zero_stream_kernel<<<n4_tail, 256>>>((float4*)(out + TOUCHED));

    // 2. Zero partition 0, leave resident in L2.
    zero_resident_kernel<<<n4_part, 256>>>((float4*)out);
    // 3. Scatter pass 0: targets in [0, PART).
    scatter_pass_kernel<<<n4_scatter, 256>>>(
        (const float4*)updates, (const int4*)mask, out, 0, PART);

    // 4. Zero partition 1, leave resident in L2.
    zero_resident_kernel<<<n4_part, 256>>>((float4*)(out + PART));
    // 5. Scatter pass 1: targets in [PART, TOUCHED).
    scatter_pass_kernel<<<n4_scatter, 256>>>(
        (const float4*)updates, (const int4*)mask, out, PART, TOUCHED);
}